// round 11
// baseline (speedup 1.0000x reference)
#include <cuda_runtime.h>
#include <math.h>

#define KC   32
#define HD   64
#define DOBS 32
#define TT   500
#define NCTA 64
#define NT   256
#define LOG2PI 1.8378770664093454835f

// ---------------- cross-step exchange state (double buffered) ----------------
__device__ float  g_lw[2][KC];
__device__ float  g_mu[2][KC][HD];
__device__ float4 g_P[2][KC][1024];     // posterior covariance P_k (full, halves written by pair)
__device__ float4 g_Mx[KC][1024];       // intra-step staging: M halves
__device__ float4 g_Pxs[KC][1024];      // intra-step staging: predicted-P halves
__device__ unsigned g_cnt = 0;
__device__ volatile unsigned g_gen = 0;
__device__ unsigned p_cnt[KC];
__device__ volatile unsigned p_gen[KC];

// Software grid barrier: 64 CTAs, all co-resident. Generation-relative (replay-safe).
__device__ __forceinline__ void grid_barrier(unsigned &gen)
{
    __threadfence();
    __syncthreads();
    if (threadIdx.x == 0) {
        unsigned prev = atomicAdd(&g_cnt, 1u);
        if (prev == NCTA - 1u) {
            g_cnt = 0u;
            __threadfence();
            g_gen = gen + 1u;
        } else {
            while (g_gen == gen) { }
        }
    }
    __syncthreads();
    __threadfence();
    gen += 1u;
}

// Pair barrier between the two CTAs of component j. Same generation pattern.
__device__ __forceinline__ void pair_barrier(int j, unsigned &pg)
{
    __threadfence();
    __syncthreads();
    if (threadIdx.x == 0) {
        unsigned prev = atomicAdd(&p_cnt[j], 1u);
        if (prev == 1u) {
            p_cnt[j] = 0u;
            __threadfence();
            p_gen[j] = pg + 1u;
        } else {
            while (p_gen[j] == pg) { }
        }
    }
    __syncthreads();
    __threadfence();
    pg += 1u;
}

// ---------------- exact symmetrization of a 64x64 shared matrix ----------------
__device__ __forceinline__ void sym64(float* sP, int tid)
{
    __syncthreads();
    for (int i = tid; i < 4096; i += NT) {
        int r = i >> 6, c = i & 63;
        if (r < c) {
            float a = 0.5f * (sP[i] + sP[c * 64 + r]);
            sP[i] = a;
            sP[c * 64 + r] = a;
        }
    }
    __syncthreads();
}

// ---------------- register-tiled shared-memory GEMM (256 threads) ----------------
// O[MR x NC] (stride os) op= sum_h Aload(r,h) * B[h*bs + c]
//   Aload(r,h) = ATR ? A[h*as + r] : A[r*as + h]
//   MODE 0: O = acc (+diag[c] when r+roff==c);  MODE 1: O -= acc;  MODE 2: O += acc.
template<int MR, int NC, int KD, int TM, int TN, bool ATR, int MODE>
__device__ __forceinline__ void mmT(const float* __restrict__ A, int as,
                                    const float* __restrict__ B, int bs,
                                    float* __restrict__ O, int os,
                                    const float* __restrict__ diag, int roff,
                                    int tid)
{
    constexpr int GX = NC / TN;
    constexpr int GY = MR / TM;
    static_assert(GX * GY == NT, "thread grid must be NT");
    const int tx = tid % GX;
    const int ty = tid / GX;

    float acc[TM][TN];
#pragma unroll
    for (int i = 0; i < TM; ++i)
#pragma unroll
        for (int jj = 0; jj < TN; ++jj) acc[i][jj] = 0.f;

#pragma unroll 16
    for (int h = 0; h < KD; ++h) {
        float a[TM];
#pragma unroll
        for (int i = 0; i < TM; ++i)
            a[i] = ATR ? A[h * as + ty * TM + i] : A[(ty * TM + i) * as + h];
        float b[TN];
        if constexpr (TN == 4) {
            float4 v = *reinterpret_cast<const float4*>(&B[h * bs + tx * 4]);
            b[0] = v.x; b[1] = v.y; b[2] = v.z; b[3] = v.w;
        } else {
#pragma unroll
            for (int jj = 0; jj < TN; ++jj) b[jj] = B[h * bs + tx * TN + jj];
        }
#pragma unroll
        for (int i = 0; i < TM; ++i)
#pragma unroll
            for (int jj = 0; jj < TN; ++jj)
                acc[i][jj] = fmaf(a[i], b[jj], acc[i][jj]);
    }

#pragma unroll
    for (int i = 0; i < TM; ++i) {
        int r = ty * TM + i;
#pragma unroll
        for (int jj = 0; jj < TN; ++jj) {
            int c = tx * TN + jj;
            if constexpr (MODE == 1) {
                O[r * os + c] -= acc[i][jj];
            } else if constexpr (MODE == 2) {
                O[r * os + c] += acc[i][jj];
            } else {
                float v = acc[i][jj];
                if (diag != nullptr && (r + roff) == c) v += diag[c];
                O[r * os + c] = v;
            }
        }
    }
}

// ---------------- observation update ----------------
// Redundant across the pair except P -= W^T W (row-half, owned rows only).
// sBW: 32 x 68 — cols 0..63: C^T P then W = L^{-1} C^T P; col 64: v then w_v.
__device__ __forceinline__ void obs_update(const float* __restrict__ y,
    float* sP, float* sC, float* sCT, float* sBW, float* sS,
    float* sR, float* sMu, float* sLd, float* sSc, int tid, int hv)
{
    // innovation v[d] = y[d] - sum_h mu[h] C[h][d]
    if (tid < 32) {
        float s = 0.f;
#pragma unroll 8
        for (int h = 0; h < 64; ++h) s = fmaf(sMu[h], sC[h * 32 + tid], s);
        sBW[tid * 68 + 64] = __ldg(&y[tid]) - s;
    }
    // X = C^T P   (32 x 64, redundant)
    mmT<32, 64, 64, 2, 4, false, 0>(sCT, 64, sP, 64, sBW, 68, nullptr, 0, tid);
    __syncthreads();
    // S = X C + diag(R)   (32 x 32, redundant)
    mmT<32, 32, 64, 2, 2, false, 0>(sBW, 68, sC, 32, sS, 33, sR, 0, tid);
    __syncthreads();
    // Cholesky of S (warp 0): 4-acc dot, shuffle pivot, rsqrt.
    if (tid < 32) {
        int r = tid;
        float pivlog = 0.f;
        for (int c = 0; c < 32; ++c) {
            float s = 0.f;
            if (r >= c) {
                s = sS[r * 33 + c];
                float s1 = 0.f, s2 = 0.f, s3 = 0.f;
                int t2 = 0;
                for (; t2 + 3 < c; t2 += 4) {
                    s  = fmaf(-sS[r * 33 + t2    ], sS[c * 33 + t2    ], s );
                    s1 = fmaf(-sS[r * 33 + t2 + 1], sS[c * 33 + t2 + 1], s1);
                    s2 = fmaf(-sS[r * 33 + t2 + 2], sS[c * 33 + t2 + 2], s2);
                    s3 = fmaf(-sS[r * 33 + t2 + 3], sS[c * 33 + t2 + 3], s3);
                }
                for (; t2 < c; ++t2)
                    s = fmaf(-sS[r * 33 + t2], sS[c * 33 + t2], s);
                s += (s1 + (s2 + s3));
            }
            float d = __shfl_sync(0xffffffffu, s, c);
            d = fmaxf(d, 1e-8f);
            float linv = rsqrtf(d);
            if (r == c) {
                pivlog = logf(d);
                sLd[c] = linv;
            }
            if (r > c) sS[r * 33 + c] = s * linv;
            __syncwarp();
        }
        float v = pivlog;
#pragma unroll
        for (int o = 16; o; o >>= 1) v += __shfl_xor_sync(0xffffffffu, v, o);
        if (r == 0) sSc[1] = v;        // logdet(S)
    }
    __syncthreads();
    // forward triangular solve: 65 RHS columns (redundant), per-thread column in regs
    if (tid < 65) {
        float x[32];
#pragma unroll
        for (int r = 0; r < 32; ++r) {
            float s = sBW[r * 68 + tid];
            float s1 = 0.f, s2 = 0.f, s3 = 0.f;
            int t2 = 0;
#pragma unroll
            for (; t2 + 3 < r; t2 += 4) {
                s  = fmaf(-sS[r * 33 + t2    ], x[t2    ], s );
                s1 = fmaf(-sS[r * 33 + t2 + 1], x[t2 + 1], s1);
                s2 = fmaf(-sS[r * 33 + t2 + 2], x[t2 + 2], s2);
                s3 = fmaf(-sS[r * 33 + t2 + 3], x[t2 + 3], s3);
            }
#pragma unroll
            for (; t2 < r; ++t2)
                s = fmaf(-sS[r * 33 + t2], x[t2], s);
            s += (s1 + (s2 + s3));
            x[r] = s * sLd[r];
        }
#pragma unroll
        for (int r = 0; r < 32; ++r) sBW[r * 68 + tid] = x[r];
    }
    __syncthreads();
    // mu += W^T w_v
    if (tid < 64) {
        float s = 0.f;
#pragma unroll 8
        for (int d = 0; d < 32; ++d)
            s = fmaf(sBW[d * 68 + tid], sBW[d * 68 + 64], s);
        sMu[tid] += s;
    }
    // log-likelihood -> lw (clamped)
    if (tid < 32) {
        float x = sBW[tid * 68 + 64];
        float v2 = x * x;
#pragma unroll
        for (int o = 16; o; o >>= 1) v2 += __shfl_xor_sync(0xffffffffu, v2, o);
        if (tid == 0) {
            float inc = -0.5f * (32.f * LOG2PI + sSc[1] + v2);
            if (!(inc > -1e30f) || !(inc < 1e30f)) inc = -1e30f;
            float nlw = sSc[0] + inc;
            if (!(nlw > -1e30f)) nlw = -1e30f;
            sSc[0] = nlw;
        }
    }
    __syncthreads();
    // P -= W^T W on OWN row half only. With symmetric pre-P and commutative fmaf,
    // the two halves form an exactly symmetric matrix — no post-sym needed.
    mmT<32, 64, 32, 2, 4, true, 1>(sBW + hv * 32, 68, sBW, 68,
                                   sP + hv * 2048, 64, nullptr, 0, tid);
    __syncthreads();
}

// ---------------- persistent kernel: 2 CTAs per mixture component ----------------
__global__ void __launch_bounds__(NT, 1)
slds_kernel(const float* __restrict__ data,
            const float* __restrict__ tlogits,
            const float* __restrict__ tmat,
            const float* __restrict__ ltn,
            const float* __restrict__ obsm,
            const float* __restrict__ lon,
            float* __restrict__ out)
{
    extern __shared__ float sh[];
    float* sA   = sh;             // 64x64
    float* sAT  = sh + 4096;      // 64x64 (A^T)
    float* sC   = sh + 8192;      // 64x32
    float* sCT  = sh + 10240;     // 32x64 (C^T)
    float* sP   = sh + 12288;     // 64x64 (full)
    float* sM   = sh + 16384;     // 64x64 (full, assembled from halves)
    float* sT   = sh + 20480;     // 32x64 (own half of A*M)
    float* sDMT = sh + 22528;     // 32x64 sqrt(r_k)*(mu_k - mu_bar)
    float* sBW  = sh + 24576;     // 32x68
    float* sS   = sh + 26752;     // 32x33
    float* sQ   = sh + 27808;     // 64
    float* sR   = sh + 27872;     // 32
    float* sMu  = sh + 27904;     // 64
    float* sMB  = sh + 27968;     // 64
    float* sTL  = sh + 28032;     // 32
    float* sRW  = sh + 28064;     // 32
    float* sSR  = sh + 28096;     // 32
    float* sLd  = sh + 28128;     // 32
    float* sSc  = sh + 28160;     // [0]=lw, [1]=logdet

    const int tid = threadIdx.x;
    const int j  = blockIdx.x >> 1;    // component
    const int hv = blockIdx.x & 1;     // row half: rows [hv*32, hv*32+32)
    unsigned gen = g_gen;
    unsigned pg  = p_gen[j];

    float4* sPf = reinterpret_cast<float4*>(sP);
    float4* sMf = reinterpret_cast<float4*>(sM);

    // ---- constants into shared, once ----
    const float* Ag = tmat + j * 4096;
    for (int i = tid; i < 4096; i += NT) {
        float v = Ag[i];
        int r = i >> 6, c = i & 63;
        sA[i] = v;
        sAT[c * 64 + r] = v;
    }
    for (int i = tid; i < 2048; i += NT) {
        float v = obsm[i];
        int h = i >> 5, d = i & 31;
        sC[i] = v;
        sCT[d * 64 + h] = v;
    }
    if (tid < 64) sQ[tid] = expf(ltn[tid]);
    if (tid < 32) sR[tid] = expf(lon[tid]);
    if (tid >= 64 && tid < 96) {  // column j of log_softmax(transition_logits)
        int k = tid - 64;
        float m = -1e30f;
        for (int c = 0; c < 32; ++c) m = fmaxf(m, tlogits[k * 32 + c]);
        float s = 0.f;
        for (int c = 0; c < 32; ++c) s += expf(tlogits[k * 32 + c] - m);
        sTL[k] = tlogits[k * 32 + j] - (m + logf(s));
    }
    if (tid >= 128 && tid < 192) sMu[tid - 128] = 0.f;
    for (int i = tid; i < 4096; i += NT) {
        int r = i >> 6, c = i & 63;
        sP[i] = (r == c) ? 1.f : 0.f;
    }
    __syncthreads();
    if (tid == 0) sSc[0] = sTL[0];
    __syncthreads();

    // t = 0 observation update
    obs_update(data, sP, sC, sCT, sBW, sS, sR, sMu, sLd, sSc, tid, hv);

    for (int t = 1; t < TT; ++t) {
        const int b = t & 1;

        // ---- export posterior of step t-1 ----
        if (hv == 0) {
            if (tid == 0) __stcg(&g_lw[b][j], sSc[0]);
            if (tid < 64) __stcg(&g_mu[b][j][tid], sMu[tid]);
        }
        __stcg(&g_P[b][j][hv * 512 + tid],       sPf[hv * 512 + tid]);
        __stcg(&g_P[b][j][hv * 512 + tid + 256], sPf[hv * 512 + tid + 256]);
        grid_barrier(gen);

        // ---- mixture weights (redundant, warp 0) ----
        if (tid < 32) {
            float lwk = sTL[tid] + __ldcg(&g_lw[b][tid]);
            float m = lwk;
#pragma unroll
            for (int o = 16; o; o >>= 1) m = fmaxf(m, __shfl_xor_sync(0xffffffffu, m, o));
            if (!(m > -9e29f)) {
                sRW[tid] = 1.f / 32.f;
                sSR[tid] = 0.1767766953f;
                if (tid == 0) sSc[0] = -1e30f;
            } else {
                float p = expf(lwk - m);
                float s = p;
#pragma unroll
                for (int o = 16; o; o >>= 1) s += __shfl_xor_sync(0xffffffffu, s, o);
                float rk = p / s;
                sRW[tid] = rk;
                sSR[tid] = sqrtf(rk);
                if (tid == 0) sSc[0] = m + logf(s);
            }
        }
        __syncthreads();

        // ---- mu_bar (redundant) ----
        if (tid < 64) {
            float s = 0.f;
#pragma unroll 8
            for (int k = 0; k < 32; ++k)
                s = fmaf(sRW[k], __ldcg(&g_mu[b][k][tid]), s);
            sMB[tid] = s;
        }
        __syncthreads();

        // ---- DMT (redundant) ----
        for (int i = tid; i < 2048; i += NT) {
            int k = i >> 6, h = i & 63;
            sDMT[i] = sSR[k] * (__ldcg(&g_mu[b][k][h]) - sMB[h]);
        }
        // ---- M own half = sum_k r_k P_k rows[hv] ----
        {
            float4 acc0 = make_float4(0.f, 0.f, 0.f, 0.f);
            float4 acc1 = acc0;
            for (int k = 0; k < 32; ++k) {
                float rk = sRW[k];
                const float4* src = g_P[b][k] + hv * 512;
                float4 v0 = __ldcg(&src[tid]);
                float4 v1 = __ldcg(&src[tid + 256]);
                acc0.x = fmaf(rk, v0.x, acc0.x); acc0.y = fmaf(rk, v0.y, acc0.y);
                acc0.z = fmaf(rk, v0.z, acc0.z); acc0.w = fmaf(rk, v0.w, acc0.w);
                acc1.x = fmaf(rk, v1.x, acc1.x); acc1.y = fmaf(rk, v1.y, acc1.y);
                acc1.z = fmaf(rk, v1.z, acc1.z); acc1.w = fmaf(rk, v1.w, acc1.w);
            }
            sMf[hv * 512 + tid]       = acc0;
            sMf[hv * 512 + tid + 256] = acc1;
        }
        __syncthreads();
        // ---- M own half += DMT^T DMT rows[hv] ----
        mmT<32, 64, 32, 2, 4, true, 2>(sDMT + hv * 32, 64, sDMT, 64,
                                       sM + hv * 2048, 64, nullptr, 0, tid);
        __syncthreads();
        // ---- exchange M halves via L2 ----
        __stcg(&g_Mx[j][hv * 512 + tid],       sMf[hv * 512 + tid]);
        __stcg(&g_Mx[j][hv * 512 + tid + 256], sMf[hv * 512 + tid + 256]);
        pair_barrier(j, pg);
        {
            int ph = hv ^ 1;
            sMf[ph * 512 + tid]       = __ldcg(&g_Mx[j][ph * 512 + tid]);
            sMf[ph * 512 + tid + 256] = __ldcg(&g_Mx[j][ph * 512 + tid + 256]);
        }
        // ---- mu = A mu_bar (redundant) ----
        if (tid < 64) {
            float s = 0.f;
#pragma unroll 8
            for (int g = 0; g < 64; ++g) s = fmaf(sA[tid * 64 + g], sMB[g], s);
            sMu[tid] = s;
        }
        __syncthreads();

        // ---- T own half = A rows[hv] * M (full) ----
        mmT<32, 64, 64, 2, 4, false, 0>(sA + hv * 2048, 64, sM, 64,
                                        sT, 64, nullptr, 0, tid);
        __syncthreads();
        // ---- P own half = T * A^T + diag(Q) ----
        mmT<32, 64, 64, 2, 4, false, 0>(sT, 64, sAT, 64,
                                        sP + hv * 2048, 64, sQ, hv * 32, tid);
        __syncthreads();
        // ---- exchange P halves, then symmetrize (identical in both CTAs) ----
        __stcg(&g_Pxs[j][hv * 512 + tid],       sPf[hv * 512 + tid]);
        __stcg(&g_Pxs[j][hv * 512 + tid + 256], sPf[hv * 512 + tid + 256]);
        pair_barrier(j, pg);
        {
            int ph = hv ^ 1;
            sPf[ph * 512 + tid]       = __ldcg(&g_Pxs[j][ph * 512 + tid]);
            sPf[ph * 512 + tid + 256] = __ldcg(&g_Pxs[j][ph * 512 + tid + 256]);
        }
        sym64(sP, tid);   // leading+trailing __syncthreads inside

        // ---- observation update ----
        obs_update(data + t * 32, sP, sC, sCT, sBW, sS, sR, sMu, sLd, sSc, tid, hv);
    }

    // ---- final logsumexp over components ----
    if (hv == 0 && tid == 0) __stcg(&g_lw[0][j], sSc[0]);
    grid_barrier(gen);
    if (blockIdx.x == 0 && tid < 32) {
        float lwk = __ldcg(&g_lw[0][tid]);
        float m = lwk;
#pragma unroll
        for (int o = 16; o; o >>= 1) m = fmaxf(m, __shfl_xor_sync(0xffffffffu, m, o));
        float s = expf(lwk - m);
#pragma unroll
        for (int o = 16; o; o >>= 1) s += __shfl_xor_sync(0xffffffffu, s, o);
        if (tid == 0) out[0] = m + logf(s);
    }
}

extern "C" void kernel_launch(void* const* d_in, const int* in_sizes, int n_in,
                              void* d_out, int out_size)
{
    // Bind inputs by element count (all six are unique) — order-independent.
    const float *data = nullptr, *tlogits = nullptr, *tmat = nullptr;
    const float *ltn = nullptr, *obsm = nullptr, *lon = nullptr;
    for (int i = 0; i < n_in; ++i) {
        switch (in_sizes[i]) {
            case TT * DOBS:        data    = (const float*)d_in[i]; break;  // 16000
            case KC * KC:          tlogits = (const float*)d_in[i]; break;  // 1024
            case KC * HD * HD:     tmat    = (const float*)d_in[i]; break;  // 131072
            case HD:               ltn     = (const float*)d_in[i]; break;  // 64
            case HD * DOBS:        obsm    = (const float*)d_in[i]; break;  // 2048
            case DOBS:             lon     = (const float*)d_in[i]; break;  // 32
        }
    }
    float* out = (float*)d_out;

    const int smem_bytes = 28164 * 4;   // ~112.7 KB dynamic shared
    cudaFuncSetAttribute(slds_kernel,
                         cudaFuncAttributeMaxDynamicSharedMemorySize, smem_bytes);
    slds_kernel<<<NCTA, NT, smem_bytes>>>(data, tlogits, tmat, ltn, obsm, lon, out);
}